// round 15
// baseline (speedup 1.0000x reference)
#include <cuda_runtime.h>
#include <cstdint>

typedef unsigned int u32;

#define Bv 2
#define Nv 2048
#define Fv 256
#define Hv 8
#define Ov 32
#define Lv 3
#define NBv (Nv/32)

// ---------------- scratch (device globals; no runtime allocation) ----------------
__device__ float g_h  [Bv*Nv*Fv];        // current node features [B][N][F]
__device__ float g_WhT[Bv*Fv*Nv];        // tf32-rounded transposed: heads [BH][O][N], out [B][F][N]
__device__ float g_s1p[4][Bv*Hv*Nv];     // raw s1 (heads: slot 0; out: 4 col-block partials)
__device__ float g_s2p[4][Bv*Hv*Nv];     // raw s2
__device__ float g_np[2][Bv*Nv*Fv];      // k-split partial numerators
__device__ float g_dp[2][Bv*Hv*Nv];      // k-split partial denominators
__device__ u32   g_mask[Bv*Nv*NBv];      // packed adjacency bits

__device__ __forceinline__ float elu1(float x) { return x > 0.f ? x : expm1f(x); }
__device__ __forceinline__ float tf32r(float x) {
    u32 u; asm("cvt.rna.tf32.f32 %0, %1;" : "=r"(u) : "f"(x));
    return __uint_as_float(u);
}
__device__ __forceinline__ u32 smem_u32(const void* p) {
    u32 a;
    asm("{ .reg .u64 t; cvta.to.shared.u64 t, %1; cvt.u32.u64 %0, t; }" : "=r"(a) : "l"(p));
    return a;
}
__device__ __forceinline__ void cp_async16(u32 saddr, const void* g) {
    asm volatile("cp.async.ca.shared.global [%0], [%1], 16;" :: "r"(saddr), "l"(g));
}
#define CP_COMMIT() asm volatile("cp.async.commit_group;" ::: "memory")
#define CP_WAIT(n)  asm volatile("cp.async.wait_group %0;" :: "n"(n) : "memory")

// ---------------- pack adjacency into bitmask ----------------
__global__ void pack_mask_kernel(const int* __restrict__ adj) {
    int idx = blockIdx.x * 256 + threadIdx.x;
    u32 bits = __ballot_sync(0xffffffffu, adj[idx] != 0);
    if ((threadIdx.x & 31) == 0) g_mask[idx >> 5] = bits;
}

// ---------------- GEMM: Wh = h @ W (MODE 0: heads, MODE 1: out) ----------------
// Double-buffered smem + register prefetch. Writes ONLY the tf32 transposed copy,
// and computes s1/s2 dot products in the epilogue.
template <int MODE>
__global__ void gemm_kernel(const float* __restrict__ xin,
                            const float* __restrict__ Wsrc,
                            const float* __restrict__ avec, int l, int use_x)
{
    __shared__ __align__(16) float As[2][16][64];
    __shared__ __align__(16) float Bs[2][16][64];
    int b = blockIdx.z;
    int by = blockIdx.y;
    int rowBase = blockIdx.x * 64;
    int colBase = by * 64;
    int t  = threadIdx.x;
    int tx = t & 15, ty = t >> 4;
    const float* hin = (use_x ? xin : g_h) + b * Nv * Fv;
    const float* Wl  = Wsrc + (MODE == 0 ? l * Hv * Fv * Ov : l * Fv * Fv);

    int r  = t >> 2;
    int kq = (t & 3) << 2;
    const float* aPtr = &hin[(rowBase + r) * Fv + kq];
    int c   = t & 63;
    int col = colBase + c;
    int kb  = t >> 6;

    float4 aR = *(const float4*)(aPtr);
    float  bR[4];
    #pragma unroll
    for (int q = 0; q < 4; q++) {
        int kk = kb + q * 4;
        bR[q] = (MODE == 0) ? Wl[((col >> 5) * Fv + kk) * Ov + (col & 31)]
                            : Wl[kk * Fv + col];
    }

    float acc[4][4] = {};
    #pragma unroll 1
    for (int it = 0; it < 16; it++) {
        int buf = it & 1;
        As[buf][kq + 0][r] = aR.x; As[buf][kq + 1][r] = aR.y;
        As[buf][kq + 2][r] = aR.z; As[buf][kq + 3][r] = aR.w;
        #pragma unroll
        for (int q = 0; q < 4; q++) Bs[buf][kb + q * 4][c] = bR[q];
        __syncthreads();

        int ktn = (it < 15) ? (it + 1) * 16 : it * 16;   // clamped prefetch
        aR = *(const float4*)(aPtr + ktn);
        #pragma unroll
        for (int q = 0; q < 4; q++) {
            int kk = ktn + kb + q * 4;
            bR[q] = (MODE == 0) ? Wl[((col >> 5) * Fv + kk) * Ov + (col & 31)]
                                : Wl[kk * Fv + col];
        }

        #pragma unroll
        for (int kk = 0; kk < 16; kk++) {
            float4 a  = *(const float4*)&As[buf][kk][ty * 4];
            float4 bb = *(const float4*)&Bs[buf][kk][tx * 4];
            float ar[4] = {a.x, a.y, a.z, a.w};
            float br[4] = {bb.x, bb.y, bb.z, bb.w};
            #pragma unroll
            for (int i = 0; i < 4; i++)
                #pragma unroll
                for (int j = 0; j < 4; j++)
                    acc[i][j] += ar[i] * br[j];
        }
    }

    // tf32-rounded transposed copy (the attention B operand)
    #pragma unroll
    for (int j = 0; j < 4; j++) {
        int cl   = colBase + tx * 4 + j;
        int rowT = (MODE == 0) ? ((b * Hv + (cl >> 5)) * Ov + (cl & 31)) : (b * Fv + cl);
        float4 pk;
        pk.x = tf32r(acc[0][j]); pk.y = tf32r(acc[1][j]);
        pk.z = tf32r(acc[2][j]); pk.w = tf32r(acc[3][j]);
        *(float4*)&g_WhT[(size_t)rowT * Nv + rowBase + ty * 4] = pk;
    }

    // fused s1/s2 epilogue
    float a1v[4], a2v[4];
    if (MODE == 0) {
        int h = 2 * by + (tx >> 3);
        const float* av = avec + (l * Hv + h) * 2 * Ov;
        #pragma unroll
        for (int j = 0; j < 4; j++) {
            a1v[j] = av[(tx & 7) * 4 + j];
            a2v[j] = av[Ov + (tx & 7) * 4 + j];
        }
    } else {
        const float* av = avec + l * 2 * Fv;
        #pragma unroll
        for (int j = 0; j < 4; j++) {
            a1v[j] = av[colBase + tx * 4 + j];
            a2v[j] = av[Fv + colBase + tx * 4 + j];
        }
    }
    #pragma unroll
    for (int i = 0; i < 4; i++) {
        float v1 = acc[i][0] * a1v[0] + acc[i][1] * a1v[1]
                 + acc[i][2] * a1v[2] + acc[i][3] * a1v[3];
        float v2 = acc[i][0] * a2v[0] + acc[i][1] * a2v[1]
                 + acc[i][2] * a2v[2] + acc[i][3] * a2v[3];
        #pragma unroll
        for (int off = 1; off <= ((MODE == 0) ? 4 : 8); off <<= 1) {
            v1 += __shfl_xor_sync(0xffffffffu, v1, off);
            v2 += __shfl_xor_sync(0xffffffffu, v2, off);
        }
        if (MODE == 0) {
            if ((tx & 7) == 0) {
                int h = 2 * by + (tx >> 3);
                int rowI = (b * Hv + h) * Nv + rowBase + ty * 4 + i;
                g_s1p[0][rowI] = v1;
                g_s2p[0][rowI] = v2;
            }
        } else {
            if (tx == 0) {
                int rowI = b * Nv + rowBase + ty * 4 + i;
                g_s1p[by][rowI] = v1;
                g_s2p[by][rowI] = v2;
            }
        }
    }
}

// ---------------- fused masked-softmax aggregation via mma.sync tf32 ----------------
// k-split 2: blockIdx.x = (rowblock<<1)|split, each CTA covers 1024 neighbors.
// 128-thread CTAs (4 warps, warp m=32). B tiles via cp.async (double-buffered).
// den computed by MMA with a constant all-ones B fragment (no scalar adds/shfl).
// Score: t = u1[n]*u2[m]; exp(leaky(e)) = max(t, t^5); mask+tf32-trunc = one LOP3.
// Partials (num, den) written to g_np/g_dp; combine kernel applies 1/den + elu.
template <int MODE>
__global__ void __launch_bounds__(128, 4) attn_mma_kernel()
{
    constexpr int BST = 68;                              // padded smem row stride (floats)
    __shared__ __align__(16) float u2s[1024];            // this CTA's neighbor half
    __shared__ __align__(16) float Bsm[2][Ov * BST];

    int t = threadIdx.x;
    int w = t >> 5, lane = t & 31;
    int gq = lane >> 2, t4 = lane & 3;
    int rblk  = blockIdx.x >> 1;
    int split = blockIdx.x & 1;
    int kbase = split * 1024;

    int b, fcBase, srow;
    const float* whT;
    if (MODE == 0) {
        int bh = blockIdx.y; b = bh >> 3; fcBase = (bh & 7) * Ov;
        srow = bh * Nv;
        whT = g_WhT + (size_t)bh * Ov * Nv;
    } else {
        b = blockIdx.z; fcBase = blockIdx.y * Ov;
        srow = b * Nv;
        whT = g_WhT + ((size_t)b * Fv + fcBase) * Nv;
    }

    int warpRow = rblk * 128 + w * 32;
    int r0 = warpRow + gq;                               // rows r0 + {0,8,16,24}

    float u1v[4];
    const u32* mrow[4];
    #pragma unroll
    for (int i = 0; i < 4; i++) {
        int rr = srow + r0 + 8 * i;
        float s = (MODE == 0) ? g_s1p[0][rr]
                : (g_s1p[0][rr] + g_s1p[1][rr] + g_s1p[2][rr] + g_s1p[3][rr]);
        u1v[i]  = __expf(0.2f * s);
        mrow[i] = g_mask + (size_t)(b * Nv + r0 + 8 * i) * NBv;
    }

    // stage this half's u2 = exp(0.2*s2) into smem
    #pragma unroll
    for (int q = 0; q < 2; q++) {
        int idx = (t + q * 128) * 4;
        float4 v0 = *(const float4*)&g_s2p[0][srow + kbase + idx];
        if (MODE == 1) {
            float4 v1 = *(const float4*)&g_s2p[1][srow + kbase + idx];
            float4 v2 = *(const float4*)&g_s2p[2][srow + kbase + idx];
            float4 v3 = *(const float4*)&g_s2p[3][srow + kbase + idx];
            v0.x += v1.x + v2.x + v3.x; v0.y += v1.y + v2.y + v3.y;
            v0.z += v1.z + v2.z + v3.z; v0.w += v1.w + v2.w + v3.w;
        }
        float4 o;
        o.x = __expf(0.2f * v0.x); o.y = __expf(0.2f * v0.y);
        o.z = __expf(0.2f * v0.z); o.w = __expf(0.2f * v0.w);
        *(float4*)&u2s[idx] = o;
    }

    // cp.async B-tile pipeline
    int prow = t >> 4, seg0 = t & 15;
    const float* bsrc = whT + kbase + seg0 * 4;
    u32 bsm0 = smem_u32(&Bsm[0][0]);
    #pragma unroll
    for (int j = 0; j < 4; j++)
        cp_async16(bsm0 + ((prow + 8 * j) * BST + seg0 * 4) * 4,
                   bsrc + (size_t)(prow + 8 * j) * Nv);
    CP_COMMIT();

    uint2 mq[4], mqn[4];
    #pragma unroll
    for (int i = 0; i < 4; i++) mq[i] = *(const uint2*)&mrow[i][kbase >> 5];

    float acc0[4][4], acc1[4][4];
    float dac0[4] = {0.f, 0.f, 0.f, 0.f}, dac1[4] = {0.f, 0.f, 0.f, 0.f};
    #pragma unroll
    for (int gi = 0; gi < 4; gi++)
        #pragma unroll
        for (int q = 0; q < 4; q++) { acc0[gi][q] = 0.f; acc1[gi][q] = 0.f; }
    const u32 one_tf = 0x3f800000u;

    #pragma unroll 1
    for (int tile = 0; tile < 16; tile++) {
        __syncthreads();                                 // all warps done with buf[(tile+1)&1]
        if (tile < 15) {
            u32 dst = bsm0 + (((tile + 1) & 1) * Ov * BST) * 4;
            const float* src = bsrc + (size_t)(tile + 1) * 64;
            #pragma unroll
            for (int j = 0; j < 4; j++)
                cp_async16(dst + ((prow + 8 * j) * BST + seg0 * 4) * 4,
                           src + (size_t)(prow + 8 * j) * Nv);
            CP_COMMIT();
            CP_WAIT(1);                                  // current tile's group done
            #pragma unroll
            for (int i = 0; i < 4; i++)
                mqn[i] = *(const uint2*)&mrow[i][(kbase >> 5) + (tile + 1) * 2];
        } else {
            CP_WAIT(0);
        }
        __syncthreads();                                 // copies visible to all warps
        const float* bd = Bsm[tile & 1];
        int kt = tile * 64;

        #pragma unroll
        for (int c = 0; c < 8; c++) {
            int bp  = (c & 3) * 8 + t4;
            int sh1 = 31 - bp;                           // bit bp
            int sh2 = 27 - bp;                           // bit bp+4
            float u2a = u2s[kt + c * 8 + t4];
            float u2b = u2s[kt + c * 8 + t4 + 4];

            u32 af[8];
            #pragma unroll
            for (int i = 0; i < 4; i++) {
                u32 wm = (c < 4) ? mq[i].x : mq[i].y;
                u32 sma = (u32)(((int)(wm << sh1)) >> 31);
                u32 smb = (u32)(((int)(wm << sh2)) >> 31);
                float ta = u1v[i] * u2a, tb = u1v[i] * u2b;
                float ta2 = ta * ta, tb2 = tb * tb;
                float pa = fmaxf(ta, ta2 * ta2 * ta);    // exp(leaky) = max(t, t^5)
                float pb = fmaxf(tb, tb2 * tb2 * tb);
                u32 ua = __float_as_uint(pa) & sma & 0xFFFFE000u;   // mask + tf32-truncate
                u32 ub = __float_as_uint(pb) & smb & 0xFFFFE000u;
                af[(i >> 1) * 4 + (i & 1)]     = ua;     // (row, k..k+3)
                af[(i >> 1) * 4 + (i & 1) + 2] = ub;     // (row, k+4..k+7)
            }

            // den via ones-B MMA (no LDS, no scalar adds)
            asm volatile(
                "mma.sync.aligned.m16n8k8.row.col.f32.tf32.tf32.f32 "
                "{%0,%1,%2,%3}, {%4,%5,%6,%7}, {%8,%9}, {%0,%1,%2,%3};"
                : "+f"(dac0[0]), "+f"(dac0[1]), "+f"(dac0[2]), "+f"(dac0[3])
                : "r"(af[0]), "r"(af[1]), "r"(af[2]), "r"(af[3]), "r"(one_tf), "r"(one_tf));
            asm volatile(
                "mma.sync.aligned.m16n8k8.row.col.f32.tf32.tf32.f32 "
                "{%0,%1,%2,%3}, {%4,%5,%6,%7}, {%8,%9}, {%0,%1,%2,%3};"
                : "+f"(dac1[0]), "+f"(dac1[1]), "+f"(dac1[2]), "+f"(dac1[3])
                : "r"(af[4]), "r"(af[5]), "r"(af[6]), "r"(af[7]), "r"(one_tf), "r"(one_tf));

            #pragma unroll
            for (int gi = 0; gi < 4; gi++) {
                const float* bpn = &bd[(gi * 8 + gq) * BST + c * 8 + t4];
                u32 b0 = __float_as_uint(bpn[0]);
                u32 b1 = __float_as_uint(bpn[4]);
                asm volatile(
                    "mma.sync.aligned.m16n8k8.row.col.f32.tf32.tf32.f32 "
                    "{%0,%1,%2,%3}, {%4,%5,%6,%7}, {%8,%9}, {%0,%1,%2,%3};"
                    : "+f"(acc0[gi][0]), "+f"(acc0[gi][1]), "+f"(acc0[gi][2]), "+f"(acc0[gi][3])
                    : "r"(af[0]), "r"(af[1]), "r"(af[2]), "r"(af[3]), "r"(b0), "r"(b1));
                asm volatile(
                    "mma.sync.aligned.m16n8k8.row.col.f32.tf32.tf32.f32 "
                    "{%0,%1,%2,%3}, {%4,%5,%6,%7}, {%8,%9}, {%0,%1,%2,%3};"
                    : "+f"(acc1[gi][0]), "+f"(acc1[gi][1]), "+f"(acc1[gi][2]), "+f"(acc1[gi][3])
                    : "r"(af[4]), "r"(af[5]), "r"(af[6]), "r"(af[7]), "r"(b0), "r"(b1));
            }
        }
        #pragma unroll
        for (int i = 0; i < 4; i++) mq[i] = mqn[i];
    }

    // den per row (cols of the ones-tile are identical; no shfl needed)
    float dv[4] = {dac0[0], dac0[2], dac1[0], dac1[2]};

    #pragma unroll
    for (int i = 0; i < 4; i++) {
        int rr = r0 + 8 * i;
        float* np = g_np[split] + ((size_t)(b * Nv + rr)) * Fv + fcBase;
        const float (*accp)[4] = (i < 2) ? acc0 : acc1;
        int base = (i & 1) * 2;
        #pragma unroll
        for (int gi = 0; gi < 4; gi++) {
            float2 v;
            v.x = accp[gi][base + 0];
            v.y = accp[gi][base + 1];
            *(float2*)&np[gi * 8 + t4 * 2] = v;
        }
        if (t4 == 0 && (MODE == 0 || blockIdx.y == 0))
            g_dp[split][srow + rr] = dv[i];
    }
}

// ---------------- combine: out = elu(num/den) (+extra elu for out stage) ----------------
template <int MODE>
__global__ void combine_kernel(float* __restrict__ dout, int fin)
{
    int i4 = blockIdx.x * 256 + threadIdx.x;
    int elem = i4 * 4;
    int row = elem >> 8;                                 // b*Nv + n
    int col = elem & 255;
    float4 n0 = ((const float4*)g_np[0])[i4];
    float4 n1 = ((const float4*)g_np[1])[i4];
    int drow;
    if (MODE == 0) {
        int bb = row >> 11, nn = row & 2047, h = col >> 5;
        drow = (bb * Hv + h) * Nv + nn;
    } else {
        drow = row;
    }
    float inv = 1.0f / (g_dp[0][drow] + g_dp[1][drow]);
    float4 v;
    v.x = elu1((n0.x + n1.x) * inv);
    v.y = elu1((n0.y + n1.y) * inv);
    v.z = elu1((n0.z + n1.z) * inv);
    v.w = elu1((n0.w + n1.w) * inv);
    if (MODE == 1) { v.x = elu1(v.x); v.y = elu1(v.y); v.z = elu1(v.z); v.w = elu1(v.w); }
    float* dst = (MODE == 1 && fin) ? dout : g_h;
    ((float4*)dst)[i4] = v;
}

// ---------------- launch ----------------
extern "C" void kernel_launch(void* const* d_in, const int* in_sizes, int n_in,
                              void* d_out, int out_size)
{
    const float* x       = (const float*)d_in[0];
    const int*   adj     = (const int*)d_in[1];
    const float* W_heads = (const float*)d_in[2];
    const float* a_heads = (const float*)d_in[3];
    const float* W_out   = (const float*)d_in[4];
    const float* a_out   = (const float*)d_in[5];
    float* out = (float*)d_out;

    pack_mask_kernel<<<(Bv * Nv * Nv) / 256, 256>>>(adj);
    const int CGRID = (Bv * Nv * Fv / 4) / 256;

    for (int l = 0; l < Lv; l++) {
        // heads stage
        gemm_kernel<0><<<dim3(Nv / 64, (Hv * Ov) / 64, Bv), 256>>>(x, W_heads, a_heads, l, l == 0 ? 1 : 0);
        attn_mma_kernel<0><<<dim3(2 * Nv / 128, Bv * Hv), 128>>>();
        combine_kernel<0><<<CGRID, 256>>>(out, 0);
        // out stage
        gemm_kernel<1><<<dim3(Nv / 64, Fv / 64, Bv), 256>>>(nullptr, W_out, a_out, l, 0);
        attn_mma_kernel<1><<<dim3(2 * Nv / 128, Fv / Ov, Bv), 128>>>();
        combine_kernel<1><<<CGRID, 256>>>(out, (l == Lv - 1) ? 1 : 0);
    }
}